// round 17
// baseline (speedup 1.0000x reference)
#include <cuda_runtime.h>
#include <cuda_fp16.h>
#include <math.h>
#include <stdint.h>

#define NINS   2048
#define TOK    16
#define EMB    512
#define HID    256
#define G4     (4*HID)      // 1024
#define PAR    8
#define LEVELS 16
#define KROWS  (NINS/LEVELS) // 128
#define T_PAD  20
// phase2 smem: A fp16 [128x264] + B fp16 [128x264] + Xp stage fp16 [128x136]
#define P2_SMEM (128*264*2 + 128*264*2 + 128*136*2)   // 169984
// phase3 smem: B fp16 [128x264] + A(h0) fp16 [128x264]
#define P3_SMEM (2*128*264*2)                          // 135168
// phase1 smem: A fp32 2 x [128x36], B fp16 2 x [128x40]
#define P1_ASTG (128*36)
#define P1_BSTG (128*40)
#define P1_SMEM (2*P1_ASTG*4 + 2*P1_BSTG*2)            // 57344

// ---------------- scratch (static device globals; no allocation) ----------------
__device__ __half g_Xp[NINS*TOK*G4];     // gate-interleaved token projections (fp16)
__device__ float g_H[NINS*HID];          // final token-LSTM hidden (fp32, phase-3a input)
__device__ __half g_Hf[NINS*HID];        // fp16 H ping
__device__ __half g_Hf2[NINS*HID];       // fp16 H pong
__device__ float g_Gx[NINS*G4];          // gate-interleaved instruction projections
__device__ float g_Hi[NINS*HID];
__device__ float g_Ci[NINS*HID];
__device__ __half g_h0h[KROWS*HID];      // gathered parent h (fp16)
__device__ float g_c0[KROWS*HID];        // gathered parent c (fp32)
__device__ __half g_WhhTokH[G4*HID];     // gate-interleaved rows, fp16
__device__ __half g_WihTokH[G4*EMB];
__device__ __half g_WhhInsH[G4*HID];
__device__ float g_WihInsP[G4*HID];      // gate-interleaved, tf32-rounded (phase-3a)
__device__ float g_biasTokP[G4];
__device__ float g_biasInsP[G4];
__device__ unsigned char g_pval[NINS*PAR];
__device__ int   g_appears[NINS];
__device__ float g_partial[64*HID];
__device__ unsigned int g_barM[16];      // per m-group barriers (phase2)
__device__ unsigned int g_bar3;          // phase3 barrier

// ---------------- helpers ----------------
__device__ __forceinline__ uint32_t cvt_tf32(float v) {
    uint32_t r;
    asm("cvt.rna.tf32.f32 %0, %1;" : "=r"(r) : "f"(v));
    return r;
}
__device__ __forceinline__ uint32_t pack_f16x2(float lo, float hi) {
    uint32_t r;
    asm("cvt.rn.f16x2.f32 %0, %1, %2;" : "=r"(r) : "f"(hi), "f"(lo));
    return r;
}
__device__ __forceinline__ void mma_tf32(float* c, uint32_t a0, uint32_t a1,
                                         uint32_t a2, uint32_t a3,
                                         uint32_t b0, uint32_t b1) {
    asm("mma.sync.aligned.m16n8k8.row.col.f32.tf32.tf32.f32 "
        "{%0,%1,%2,%3}, {%4,%5,%6,%7}, {%8,%9}, {%0,%1,%2,%3};"
        : "+f"(c[0]), "+f"(c[1]), "+f"(c[2]), "+f"(c[3])
        : "r"(a0), "r"(a1), "r"(a2), "r"(a3), "r"(b0), "r"(b1));
}
__device__ __forceinline__ void mma_f16(float* c, uint32_t a0, uint32_t a1,
                                        uint32_t a2, uint32_t a3,
                                        uint32_t b0, uint32_t b1) {
    asm("mma.sync.aligned.m16n8k16.row.col.f32.f16.f16.f32 "
        "{%0,%1,%2,%3}, {%4,%5,%6,%7}, {%8,%9}, {%0,%1,%2,%3};"
        : "+f"(c[0]), "+f"(c[1]), "+f"(c[2]), "+f"(c[3])
        : "r"(a0), "r"(a1), "r"(a2), "r"(a3), "r"(b0), "r"(b1));
}
__device__ __forceinline__ void cp_async16(void* smem, const void* gmem) {
    uint32_t s = (uint32_t)__cvta_generic_to_shared(smem);
    asm volatile("cp.async.cg.shared.global [%0], [%1], 16;\n" :: "r"(s), "l"(gmem));
}

// ---------------- grid barrier (proven: fence + atomicAdd poll) ----------------
__device__ __forceinline__ void grid_sync(unsigned int* bar, unsigned int target) {
    __threadfence();
    __syncthreads();
    if (threadIdx.x == 0) {
        atomicAdd(bar, 1u);
        while (atomicAdd(bar, 0u) < target) { __nanosleep(32); }
    }
    __syncthreads();
    __threadfence();
}

// ---------------- fp16 GEMM inner loop: acc += Ast[128x256] @ Bres[128x256]^T ----------------
__device__ __forceinline__ void f16_gemm_16k(
    const __half* __restrict__ Ast, const __half* __restrict__ Bres,
    float (&acc)[4][4][4], int wm, int wn, int g, int tig)
{
#pragma unroll
    for (int kt = 0; kt < 16; kt++) {
        const int k0 = kt * 16;
        uint32_t b0[4], b1[4];
#pragma unroll
        for (int ni = 0; ni < 4; ni++) {
            const __half* bp = Bres + (wn + ni*8 + g) * 264 + k0;
            b0[ni] = *(const uint32_t*)(bp + 2*tig);
            b1[ni] = *(const uint32_t*)(bp + 8 + 2*tig);
        }
        uint32_t a0[4], a1[4], a2[4], a3[4];
#pragma unroll
        for (int mi = 0; mi < 4; mi++) {
            const __half* r0p = Ast + (wm + mi*16 + g) * 264 + k0;
            const __half* r1p = Ast + (wm + mi*16 + 8 + g) * 264 + k0;
            a0[mi] = *(const uint32_t*)(r0p + 2*tig);
            a1[mi] = *(const uint32_t*)(r1p + 2*tig);
            a2[mi] = *(const uint32_t*)(r0p + 8 + 2*tig);
            a3[mi] = *(const uint32_t*)(r1p + 8 + 2*tig);
        }
#pragma unroll
        for (int mi = 0; mi < 4; mi++)
#pragma unroll
            for (int ni = 0; ni < 4; ni++)
                mma_f16(acc[mi][ni], a0[mi], a1[mi], a2[mi], a3[mi], b0[ni], b1[ni]);
    }
}

// ---------------- prep: pval normalize + appears + barrier reset ----------------
__global__ void prep_kernel(const unsigned char* __restrict__ pv_raw,
                            const int* __restrict__ pidx)
{
    __shared__ int s_hi, s_b0;
    __shared__ int s_app[NINS];
    int tid = threadIdx.x;
    if (tid < 16) g_barM[tid] = 0u;
    if (tid == 16) g_bar3 = 0u;
    int hi = 0, b0 = 0;
    for (int i = 256 + tid; i < 4096; i += 256) {
        hi |= pv_raw[4*i+1] | pv_raw[4*i+2] | pv_raw[4*i+3];
        b0 |= pv_raw[4*i+0];
    }
    if (tid == 0) { s_hi = 0; s_b0 = 0; }
    __syncthreads();
    if (hi) atomicOr(&s_hi, 1);
    if (b0) atomicOr(&s_b0, 1);
    __syncthreads();
    int mode = (s_hi == 0) ? 0 : (s_b0 == 0 ? 1 : 2);
    for (int i = tid; i < NINS*PAR; i += 256) {
        unsigned char v;
        if (mode == 0)      v = (((const int*)pv_raw)[i]   != 0);
        else if (mode == 1) v = (((const float*)pv_raw)[i] != 0.0f);
        else                v = (pv_raw[i] != 0);
        g_pval[i] = v;
    }
    for (int i = tid; i < NINS; i += 256) s_app[i] = 0;
    __syncthreads();
    for (int i = tid; i < NINS*PAR; i += 256) {
        if (g_pval[i]) atomicAdd(&s_app[pidx[i]], 1);
    }
    __syncthreads();
    for (int i = tid; i < NINS; i += 256) g_appears[i] = s_app[i];
}

// ---------------- merged weight/bias prep ----------------
__global__ void permAll_kernel(const float* __restrict__ Whh_tok,
                               const float* __restrict__ Whh_ins,
                               const float* __restrict__ Wih_tok,
                               const float* __restrict__ Wih_ins,
                               const float* __restrict__ bih_tok,
                               const float* __restrict__ bhh_tok,
                               const float* __restrict__ bih_ins,
                               const float* __restrict__ bhh_ins)
{
    int np = blockIdx.x;
    int n  = (np & 3) * HID + (np >> 2);
    int c  = threadIdx.x;
    g_WhhTokH[(size_t)np * HID + c] = __float2half_rn(Whh_tok[(size_t)n * HID + c]);
    g_WhhInsH[(size_t)np * HID + c] = __float2half_rn(Whh_ins[(size_t)n * HID + c]);
    g_WihInsP[(size_t)np * HID + c] = __uint_as_float(cvt_tf32(Wih_ins[(size_t)n * HID + c]));
    g_WihTokH[(size_t)np * EMB + c]       = __float2half_rn(Wih_tok[(size_t)n * EMB + c]);
    g_WihTokH[(size_t)np * EMB + 256 + c] = __float2half_rn(Wih_tok[(size_t)n * EMB + 256 + c]);
    if (c == 0) {
        g_biasTokP[np] = bih_tok[n] + bhh_tok[n];
        g_biasInsP[np] = bih_ins[n] + bhh_ins[n];
    }
}

// ============================================================================
// tf32 tile GEMM (phase-3a only)
// ============================================================================
template<int KDIM>
__device__ __forceinline__ void tile_gemm(
    const float* __restrict__ A, const float* __restrict__ B,
    int bm, int bn, float (&acc)[4][4][4], float* As, float* Bs)
{
    const int tid  = threadIdx.x;
    const int lane = tid & 31;
    const int warp = tid >> 5;
    const int wm = (warp >> 2) * 64;
    const int wn = (warp & 3) * 32;
    const int g   = lane >> 2;
    const int tig = lane & 3;
    const int NT = KDIM / 16;

#pragma unroll
    for (int u = 0; u < 2; u++) {
        int idx = u * 256 + tid;
        int r = idx >> 2, c4 = idx & 3;
        cp_async16(As + r * T_PAD + c4 * 4, A + (size_t)(bm + r) * KDIM + c4 * 4);
        cp_async16(Bs + r * T_PAD + c4 * 4, B + (size_t)(bn + r) * KDIM + c4 * 4);
    }
    asm volatile("cp.async.commit_group;\n");

    for (int kt = 0; kt < NT; kt++) {
        int cur = kt & 1;
        if (kt + 1 < NT) {
            int nxt = (kt + 1) & 1;
            const float* Ap = A + (size_t)bm * KDIM + (kt + 1) * 16;
            const float* Bp = B + (size_t)bn * KDIM + (kt + 1) * 16;
#pragma unroll
            for (int u = 0; u < 2; u++) {
                int idx = u * 256 + tid;
                int r = idx >> 2, c4 = idx & 3;
                cp_async16(As + nxt * 128 * T_PAD + r * T_PAD + c4 * 4,
                           Ap + (size_t)r * KDIM + c4 * 4);
                cp_async16(Bs + nxt * 128 * T_PAD + r * T_PAD + c4 * 4,
                           Bp + (size_t)r * KDIM + c4 * 4);
            }
            asm volatile("cp.async.commit_group;\n");
            asm volatile("cp.async.wait_group 1;\n");
        } else {
            asm volatile("cp.async.wait_group 0;\n");
        }
        __syncthreads();

        const float* Asb = As + cur * 128 * T_PAD;
        const float* Bsb = Bs + cur * 128 * T_PAD;
#pragma unroll
        for (int ks = 0; ks < 2; ks++) {
            const int k0 = ks * 8;
            uint32_t bf[4][2];
#pragma unroll
            for (int ni = 0; ni < 4; ni++) {
                bf[ni][0] = __float_as_uint(Bsb[(wn + ni*8 + g) * T_PAD + k0 + tig]);
                bf[ni][1] = __float_as_uint(Bsb[(wn + ni*8 + g) * T_PAD + k0 + tig + 4]);
            }
            uint32_t af[4][4];
#pragma unroll
            for (int mi = 0; mi < 4; mi++) {
                int r0 = (wm + mi*16 + g) * T_PAD + k0;
                int r1 = (wm + mi*16 + 8 + g) * T_PAD + k0;
                af[mi][0] = cvt_tf32(Asb[r0 + tig]);
                af[mi][1] = cvt_tf32(Asb[r1 + tig]);
                af[mi][2] = cvt_tf32(Asb[r0 + tig + 4]);
                af[mi][3] = cvt_tf32(Asb[r1 + tig + 4]);
            }
#pragma unroll
            for (int mi = 0; mi < 4; mi++)
#pragma unroll
                for (int ni = 0; ni < 4; ni++)
                    mma_tf32(acc[mi][ni], af[mi][0], af[mi][1], af[mi][2], af[mi][3],
                             bf[ni][0], bf[ni][1]);
        }
        __syncthreads();
    }
}

// ============================================================================
// Phase-1 fp16 GEMM: Xp_f16[M,1024] = A_f32[M,512] @ B_f16[1024,512]^T + bias
// ============================================================================
__global__ __launch_bounds__(256, 2) void p1_f16_kernel(
    const float* __restrict__ A, const float* __restrict__ bias)
{
    extern __shared__ float dsm[];
    float* As = dsm;                                 // 2 x [128 x 36] fp32
    __half* Bs = (__half*)(dsm + 2*P1_ASTG);         // 2 x [128 x 40] fp16

    const int KDIM = EMB;
    const int tid  = threadIdx.x;
    const int lane = tid & 31;
    const int warp = tid >> 5;
    const int wm = (warp >> 2) * 64;
    const int wn = (warp & 3) * 32;
    const int g   = lane >> 2;
    const int tig = lane & 3;
    const int bm = blockIdx.y * 128;
    const int bn = blockIdx.x * 128;
    const int NT = KDIM / 32;

    float acc[4][4][4];
#pragma unroll
    for (int mi = 0; mi < 4; mi++)
#pragma unroll
        for (int ni = 0; ni < 4; ni++)
#pragma unroll
            for (int r = 0; r < 4; r++) acc[mi][ni][r] = 0.0f;

#pragma unroll
    for (int u = 0; u < 4; u++) {
        int idx = u * 256 + tid;
        int r = idx >> 3, c4 = idx & 7;
        cp_async16(As + r * 36 + c4 * 4, A + (size_t)(bm + r) * KDIM + c4 * 4);
    }
#pragma unroll
    for (int u = 0; u < 2; u++) {
        int idx = u * 256 + tid;
        int r = idx >> 2, c8 = idx & 3;
        cp_async16(Bs + r * 40 + c8 * 8, g_WihTokH + (size_t)(bn + r) * KDIM + c8 * 8);
    }
    asm volatile("cp.async.commit_group;\n");

    for (int kt = 0; kt < NT; kt++) {
        int cur = kt & 1;
        if (kt + 1 < NT) {
            int nxt = (kt + 1) & 1;
            const float* Ap = A + (size_t)bm * KDIM + (kt + 1) * 32;
            const __half* Bp = g_WihTokH + (size_t)bn * KDIM + (kt + 1) * 32;
#pragma unroll
            for (int u = 0; u < 4; u++) {
                int idx = u * 256 + tid;
                int r = idx >> 3, c4 = idx & 7;
                cp_async16(As + nxt * P1_ASTG + r * 36 + c4 * 4,
                           Ap + (size_t)r * KDIM + c4 * 4);
            }
#pragma unroll
            for (int u = 0; u < 2; u++) {
                int idx = u * 256 + tid;
                int r = idx >> 2, c8 = idx & 3;
                cp_async16(Bs + nxt * P1_BSTG + r * 40 + c8 * 8,
                           Bp + (size_t)r * KDIM + c8 * 8);
            }
            asm volatile("cp.async.commit_group;\n");
            asm volatile("cp.async.wait_group 1;\n");
        } else {
            asm volatile("cp.async.wait_group 0;\n");
        }
        __syncthreads();

        const float* Asb = As + cur * P1_ASTG;
        const __half* Bsb = Bs + cur * P1_BSTG;
#pragma unroll
        for (int ks = 0; ks < 2; ks++) {
            const int k0 = ks * 16;
            uint32_t b0[4], b1[4];
#pragma unroll
            for (int ni = 0; ni < 4; ni++) {
                const __half* bp = Bsb + (wn + ni*8 + g) * 40 + k0;
                b0[ni] = *(const uint32_t*)(bp + 2*tig);
                b1[ni] = *(const uint32_t*)(bp + 8 + 2*tig);
            }
            uint32_t a0[4], a1[4], a2[4], a3[4];
#pragma unroll
            for (int mi = 0; mi < 4; mi++) {
                const float* r0p = Asb + (wm + mi*16 + g) * 36 + k0;
                const float* r1p = Asb + (wm + mi*16 + 8 + g) * 36 + k0;
                a0[mi] = pack_f16x2(r0p[2*tig],     r0p[2*tig + 1]);
                a1[mi] = pack_f16x2(r1p[2*tig],     r1p[2*tig + 1]);
                a2[mi] = pack_f16x2(r0p[8 + 2*tig], r0p[9 + 2*tig]);
                a3[mi] = pack_f16x2(r1p[8 + 2*tig], r1p[9 + 2*tig]);
            }
#pragma unroll
            for (int mi = 0; mi < 4; mi++)
#pragma unroll
                for (int ni = 0; ni < 4; ni++)
                    mma_f16(acc[mi][ni], a0[mi], a1[mi], a2[mi], a3[mi], b0[ni], b1[ni]);
        }
        __syncthreads();
    }

    // epilogue: bias + fp16 write
#pragma unroll
    for (int mi = 0; mi < 4; mi++) {
        int r0 = bm + wm + mi*16 + g;
        int r1 = r0 + 8;
#pragma unroll
        for (int ni = 0; ni < 4; ni++) {
            int c = bn + wn + ni*8 + tig*2;
            float bb0 = bias[c];
            float bb1 = bias[c+1];
            __half2 v0 = __floats2half2_rn(acc[mi][ni][0] + bb0, acc[mi][ni][1] + bb1);
            __half2 v1 = __floats2half2_rn(acc[mi][ni][2] + bb0, acc[mi][ni][3] + bb1);
            *(__half2*)(g_Xp + (size_t)r0 * G4 + c) = v0;
            *(__half2*)(g_Xp + (size_t)r1 * G4 + c) = v1;
        }
    }
}

// ============================================================================
// Phase-2 persistent: 16 token-LSTM steps, 128 blocks, m-group barriers.
// ============================================================================
__global__ __launch_bounds__(256) void phase2_kernel()
{
    extern __shared__ float dsm[];
    __half* Ares = (__half*)dsm;                        // [128 x 264]
    __half* Bres = Ares + 128*264;                      // [128 x 264]
    __half* Xst  = Bres + 128*264;                      // [128 x 136]

    const int tid  = threadIdx.x;
    const int lane = tid & 31;
    const int warp = tid >> 5;
    const int wm = (warp >> 2) * 64;
    const int wn = (warp & 3) * 32;
    const int g   = lane >> 2;
    const int tig = lane & 3;
    const int mg = blockIdx.x >> 3;
    const int bm = mg * 128;
    const int bn = (blockIdx.x & 7) * 128;

    // resident B
#pragma unroll
    for (int u = 0; u < 16; u++) {
        int idx = u * 256 + tid;
        int r = idx >> 5, c8 = idx & 31;
        cp_async16(Bres + r * 264 + c8 * 8, g_WhhTokH + (size_t)(bn + r) * HID + c8 * 8);
    }
    asm volatile("cp.async.commit_group;\n");
    asm volatile("cp.async.wait_group 0;\n");
    __syncthreads();

    float cst[4][4];
#pragma unroll
    for (int mi = 0; mi < 4; mi++)
#pragma unroll
        for (int ni = 0; ni < 4; ni++) cst[mi][ni] = 0.0f;

    for (int t = 0; t < TOK; t++) {
        float acc[4][4][4];
#pragma unroll
        for (int mi = 0; mi < 4; mi++)
#pragma unroll
            for (int ni = 0; ni < 4; ni++)
#pragma unroll
                for (int r = 0; r < 4; r++) acc[mi][ni][r] = 0.0f;

        const __half* Aglob = (t & 1) ? g_Hf2 : g_Hf;
        __half* Hdst = (t & 1) ? g_Hf : g_Hf2;

        if (t > 0) {
#pragma unroll
            for (int u = 0; u < 16; u++) {
                int idx = u * 256 + tid;
                int r = idx >> 5, c8 = idx & 31;
                cp_async16(Ares + r * 264 + c8 * 8, Aglob + (size_t)(bm + r) * HID + c8 * 8);
            }
            asm volatile("cp.async.commit_group;\n");
        }
        // Xp stage: 128 rows x 128 halves
#pragma unroll
        for (int u = 0; u < 8; u++) {
            int idx = u * 256 + tid;
            int r = idx >> 4, c8 = idx & 15;
            cp_async16(Xst + r * 136 + c8 * 8,
                       g_Xp + ((size_t)(bm + r) * TOK + t) * G4 + bn + c8 * 8);
        }
        asm volatile("cp.async.commit_group;\n");

        if (t > 0) {
            asm volatile("cp.async.wait_group 1;\n");
            __syncthreads();
            f16_gemm_16k(Ares, Bres, acc, wm, wn, g, tig);
        }

        asm volatile("cp.async.wait_group 0;\n");
        __syncthreads();

#pragma unroll
        for (int mi = 0; mi < 4; mi++) {
#pragma unroll
            for (int ni = 0; ni < 4; ni++) {
                float c0 = acc[mi][ni][0], c1 = acc[mi][ni][1];
                float c2 = acc[mi][ni][2], c3 = acc[mi][ni][3];
                float x0 = __shfl_xor_sync(0xffffffffu, c0, 1);
                float x1 = __shfl_xor_sync(0xffffffffu, c1, 1);
                float x2 = __shfl_xor_sync(0xffffffffu, c2, 1);
                float x3 = __shfl_xor_sync(0xffffffffu, c3, 1);
                int q = tig >> 1;
                int h = (bn + wn + ni*8 + q*4) >> 2;
                int row, rl;
                float gi, gf, gg, go;
                if ((tig & 1) == 0) {
                    rl = wm + mi*16 + g;
                    gi = c0; gf = c1; gg = x0; go = x1;
                } else {
                    rl = wm + mi*16 + 8 + g;
                    gi = x2; gf = x3; gg = c2; go = c3;
                }
                row = bm + rl;
                const __half2* xp = (const __half2*)(Xst + rl * 136 + (wn + ni*8 + q*4));
                float2 xlo = __half22float2(xp[0]);
                float2 xhi = __half22float2(xp[1]);
                gi += xlo.x;
                gf += xlo.y;
                gg += xhi.x;
                go += xhi.y;
                float c = cst[mi][ni];
                float si = 1.0f / (1.0f + expf(-gi));
                float sf = 1.0f / (1.0f + expf(-gf));
                float so = 1.0f / (1.0f + expf(-go));
                float cn = sf * c + si * tanhf(gg);
                float hn = so * tanhf(cn);
                cst[mi][ni] = cn;
                if (t == TOK - 1)
                    g_H[(size_t)row * HID + h] = hn;
                else
                    Hdst[(size_t)row * HID + h] = __float2half_rn(hn);
            }
        }

        if (t + 1 < TOK)
            grid_sync(&g_barM[mg], 8u * (unsigned)(t + 1));
    }
}

// ============================================================================
// Plain tf32 GEMM kernel (phase-3a Gx): C = A@B^T + bias (permuted)
// ============================================================================
template<int KDIM>
__global__ __launch_bounds__(256, 2) void mma_plain_kernel(
    const float* __restrict__ A, const float* __restrict__ B,
    float* __restrict__ Cout, const float* __restrict__ bias)
{
    __shared__ float As[2*128*T_PAD];
    __shared__ float Bs[2*128*T_PAD];
    const int bm = blockIdx.y * 128;
    const int bn = blockIdx.x * 128;
    const int lane = threadIdx.x & 31;
    const int warp = threadIdx.x >> 5;
    const int wm = (warp >> 2) * 64;
    const int wn = (warp & 3) * 32;
    const int g   = lane >> 2;
    const int tig = lane & 3;

    float acc[4][4][4];
#pragma unroll
    for (int mi = 0; mi < 4; mi++)
#pragma unroll
        for (int ni = 0; ni < 4; ni++)
#pragma unroll
            for (int r = 0; r < 4; r++) acc[mi][ni][r] = 0.0f;

    tile_gemm<KDIM>(A, B, bm, bn, acc, As, Bs);

#pragma unroll
    for (int mi = 0; mi < 4; mi++) {
        int r0 = bm + wm + mi*16 + g;
        int r1 = r0 + 8;
#pragma unroll
        for (int ni = 0; ni < 4; ni++) {
            int c = bn + wn + ni*8 + tig*2;
            float bb0 = bias[c];
            float bb1 = bias[c+1];
            float2 v0 = make_float2(acc[mi][ni][0] + bb0, acc[mi][ni][1] + bb1);
            float2 v1 = make_float2(acc[mi][ni][2] + bb0, acc[mi][ni][3] + bb1);
            *(float2*)(Cout + (size_t)r0 * G4 + c) = v0;
            *(float2*)(Cout + (size_t)r1 * G4 + c) = v1;
        }
    }
}

// ============================================================================
// Phase-3 persistent: all 16 DAG levels, 8 blocks, proven barrier.
// Whh_ins fp16 smem-resident for all levels; h0 gathered to fp16 global,
// staged to smem via cp.async.cg (L1-bypass); c0 via __ldcg.
// ============================================================================
__global__ __launch_bounds__(256) void phase3_kernel(const int* __restrict__ pidx)
{
    extern __shared__ float dsm[];
    __half* Bres = (__half*)dsm;            // [128 x 264]
    __half* Ast  = Bres + 128*264;          // [128 x 264]

    const int tid  = threadIdx.x;
    const int lane = tid & 31;
    const int warp = tid >> 5;
    const int wm = (warp >> 2) * 64;
    const int wn = (warp & 3) * 32;
    const int g   = lane >> 2;
    const int tig = lane & 3;
    const int bn = blockIdx.x * 128;

    // resident B (Whh_ins fp16)
#pragma unroll
    for (int u = 0; u < 16; u++) {
        int idx = u * 256 + tid;
        int r = idx >> 5, c8 = idx & 31;
        cp_async16(Bres + r * 264 + c8 * 8, g_WhhInsH + (size_t)(bn + r) * HID + c8 * 8);
    }
    asm volatile("cp.async.commit_group;\n");
    asm volatile("cp.async.wait_group 0;\n");
    __syncthreads();

    for (int l = 0; l < LEVELS; l++) {
        // gather: this block handles 16 rows x 256 h
        for (int idx = tid; idx < 16 * HID; idx += 256) {
            int rl = idx >> 8;
            int h  = idx & 255;
            int r  = blockIdx.x * 16 + rl;       // row within level
            int row = l * KROWS + r;
            float mh = -1e30f, mc = -1e30f;
            int has = 0;
#pragma unroll
            for (int p = 0; p < PAR; p++) {
                if (g_pval[row*PAR + p]) {
                    int pi = pidx[row*PAR + p];
                    has = 1;
                    mh = fmaxf(mh, __ldcg(g_Hi + (size_t)pi*HID + h));
                    mc = fmaxf(mc, __ldcg(g_Ci + (size_t)pi*HID + h));
                }
            }
            g_h0h[r*HID + h] = __float2half_rn(has ? mh : 0.0f);
            g_c0[r*HID + h]  = has ? mc : 0.0f;
        }
        grid_sync(&g_bar3, 8u * (unsigned)(2*l + 1));

        // stage A (full h0 tile, fp16)
#pragma unroll
        for (int u = 0; u < 16; u++) {
            int idx = u * 256 + tid;
            int r = idx >> 5, c8 = idx & 31;
            cp_async16(Ast + r * 264 + c8 * 8, g_h0h + (size_t)r * HID + c8 * 8);
        }
        asm volatile("cp.async.commit_group;\n");
        asm volatile("cp.async.wait_group 0;\n");
        __syncthreads();

        float acc[4][4][4];
#pragma unroll
        for (int mi = 0; mi < 4; mi++)
#pragma unroll
            for (int ni = 0; ni < 4; ni++)
#pragma unroll
                for (int r = 0; r < 4; r++) acc[mi][ni][r] = 0.0f;

        f16_gemm_16k(Ast, Bres, acc, wm, wn, g, tig);

        // fused epilogue
        const float* Gxl = g_Gx + (size_t)l * KROWS * G4;
        float* Hil = g_Hi + (size_t)l * KROWS * HID;
        float* Cil = g_Ci + (size_t)l * KROWS * HID;
#pragma unroll
        for (int mi = 0; mi < 4; mi++) {
#pragma unroll
            for (int ni = 0; ni < 4; ni++) {
                float c0 = acc[mi][ni][0], c1 = acc[mi][ni][1];
                float c2 = acc[mi][ni][2], c3 = acc[mi][ni][3];
                float x0 = __shfl_xor_sync(0xffffffffu, c0, 1);
                float x1 = __shfl_xor_sync(0xffffffffu, c1, 1);
                float x2 = __shfl_xor_sync(0xffffffffu, c2, 1);
                float x3 = __shfl_xor_sync(0xffffffffu, c3, 1);
                int q = tig >> 1;
                int h = (bn + wn + ni*8 + q*4) >> 2;
                int rl;
                float gi, gf, gg, go;
                if ((tig & 1) == 0) {
                    rl = wm + mi*16 + g;
                    gi = c0; gf = c1; gg = x0; go = x1;
                } else {
                    rl = wm + mi*16 + 8 + g;
                    gi = x2; gf = x3; gg = c2; go = c3;
                }
                const float4 ad4 = *(const float4*)(Gxl + (size_t)rl * G4 + 4*h);
                gi += ad4.x;
                gf += ad4.y;
                gg += ad4.z;
                go += ad4.w;
                float c = __ldcg(g_c0 + rl*HID + h);
                float si = 1.0f / (1.0f + expf(-gi));
                float sf = 1.0f / (1.0f + expf(-gf));
                float so = 1.0f / (1.0f + expf(-go));
                float cn = sf * c + si * tanhf(gg);
                float hn = so * tanhf(cn);
                Cil[(size_t)rl * HID + h] = cn;
                Hil[(size_t)rl * HID + h] = hn;
            }
        }
        grid_sync(&g_bar3, 8u * (unsigned)(2*l + 2));
    }
}

// ---------------- final: masked max over roots, then dot with Wlin ----------------
__global__ void final1_kernel()
{
    int b = blockIdx.x;
    int h = threadIdx.x;
    float m = -1e30f;
    for (int r = b*32; r < b*32 + 32; r++)
        if (g_appears[r] == 0) m = fmaxf(m, g_Hi[(size_t)r*HID + h]);
    g_partial[b*HID + h] = m;
}

__global__ void final2_kernel(const float* __restrict__ Wlin,
                              const float* __restrict__ blin,
                              float* __restrict__ out)
{
    int h = threadIdx.x;
    float m = -1e30f;
    for (int b = 0; b < 64; b++) m = fmaxf(m, g_partial[b*HID + h]);
    float v = m * Wlin[h];
    __shared__ float s[256];
    s[h] = v;
    __syncthreads();
    for (int st = 128; st > 0; st >>= 1) {
        if (h < st) s[h] += s[h + st];
        __syncthreads();
    }
    if (h == 0) out[0] = s[0] + blin[0];
}

// ---------------- launch ----------------
extern "C" void kernel_launch(void* const* d_in, const int* in_sizes, int n_in,
                              void* d_out, int out_size)
{
    const float* tokens   = (const float*)d_in[0];
    const int*   pidx     = (const int*)  d_in[1];
    const unsigned char* pval = (const unsigned char*)d_in[2];
    const float* Wih_tok  = (const float*)d_in[3];
    const float* Whh_tok  = (const float*)d_in[4];
    const float* bih_tok  = (const float*)d_in[5];
    const float* bhh_tok  = (const float*)d_in[6];
    const float* Wih_ins  = (const float*)d_in[7];
    const float* Whh_ins  = (const float*)d_in[8];
    const float* bih_ins  = (const float*)d_in[9];
    const float* bhh_ins  = (const float*)d_in[10];
    const float* Wlin     = (const float*)d_in[11];
    const float* blin     = (const float*)d_in[12];
    float* out = (float*)d_out;

    float *pH, *pGx, *pWihInsP, *pBT, *pBI;
    cudaGetSymbolAddress((void**)&pH,       g_H);
    cudaGetSymbolAddress((void**)&pGx,      g_Gx);
    cudaGetSymbolAddress((void**)&pWihInsP, g_WihInsP);
    cudaGetSymbolAddress((void**)&pBT,      g_biasTokP);
    cudaGetSymbolAddress((void**)&pBI,      g_biasInsP);

    cudaFuncSetAttribute(phase2_kernel, cudaFuncAttributeMaxDynamicSharedMemorySize, P2_SMEM);
    cudaFuncSetAttribute(phase3_kernel, cudaFuncAttributeMaxDynamicSharedMemorySize, P3_SMEM);
    cudaFuncSetAttribute(p1_f16_kernel, cudaFuncAttributeMaxDynamicSharedMemorySize, P1_SMEM);

    prep_kernel<<<1, 256>>>(pval, pidx);
    permAll_kernel<<<G4, 256>>>(Whh_tok, Whh_ins, Wih_tok, Wih_ins,
                                bih_tok, bhh_tok, bih_ins, bhh_ins);

    // Phase 1: Xp (gate-interleaved fp16) = tokens @ WihTokH^T + biasTokP
    p1_f16_kernel<<<dim3(8, 256), 256, P1_SMEM>>>(tokens, pBT);

    // Phase 2: persistent token-LSTM recurrence (final hidden -> g_H fp32)
    phase2_kernel<<<128, 256, P2_SMEM>>>();

    // Phase 3a: Gx (gate-interleaved fp32) = ins_embed @ WihInsP^T + biasInsP (tf32)
    mma_plain_kernel<HID><<<dim3(8, 16), 256>>>(pH, pWihInsP, pGx, pBI);

    // Phase 3b: persistent DAG levels (fp16)
    phase3_kernel<<<8, 256, P3_SMEM>>>(pidx);

    final1_kernel<<<64, 256>>>();
    final2_kernel<<<1, 256>>>(Wlin, blin, out);
}